// round 7
// baseline (speedup 1.0000x reference)
#include <cuda_runtime.h>
#include <cuda_bf16.h>
#include <math.h>
#include <stdint.h>

#define Hh 256
#define N2d 32
#define Bb 8
#define Ll 4096
#define NCH 4                 // chunks per (b,h)
#define LCH (Ll/NCH)          // 1024

// -------- scratch (no allocations allowed) --------
__device__ float g_lam_re[Hh*N2d], g_lam_im[Hh*N2d];
__device__ float g_lamK_re[Hh*N2d], g_lamK_im[Hh*N2d];   // lambda^1024
__device__ float g_c_re[Hh*N2d],   g_c_im[Hh*N2d];
__device__ float g_S_re[Bb*Hh*3*N2d], g_S_im[Bb*Hh*3*N2d];      // chunk-local end states
__device__ float g_Ti_re[Bb*Hh*NCH*N2d], g_Ti_im[Bb*Hh*NCH*N2d]; // chunk initial states
__device__ __align__(16) __nv_bfloat16 g_Whi[2*Hh*Hh], g_Wlo[2*Hh*Hh];
// Y natural layout: [b][h][l]. hi/lo bf16 split of post-GELU activations.
__device__ __align__(16) __nv_bfloat16 g_Yhi[(size_t)Bb*Hh*Ll];
__device__ __align__(16) __nv_bfloat16 g_Ylo[(size_t)Bb*Hh*Ll];

__device__ __forceinline__ uint32_t smem_u32(const void* p) {
    uint32_t a;
    asm("{ .reg .u64 t; cvta.to.shared.u64 t, %1; cvt.u32.u64 %0, t; }" : "=r"(a) : "l"(p));
    return a;
}
__device__ __forceinline__ void ldsm4(uint32_t* r, uint32_t a) {
    asm volatile("ldmatrix.sync.aligned.m8n8.x4.shared.b16 {%0,%1,%2,%3}, [%4];"
                 : "=r"(r[0]), "=r"(r[1]), "=r"(r[2]), "=r"(r[3]) : "r"(a));
}
__device__ __forceinline__ void ldsm4t(uint32_t* r, uint32_t a) {
    asm volatile("ldmatrix.sync.aligned.m8n8.x4.trans.shared.b16 {%0,%1,%2,%3}, [%4];"
                 : "=r"(r[0]), "=r"(r[1]), "=r"(r[2]), "=r"(r[3]) : "r"(a));
}
__device__ __forceinline__ void mma16816(float* c, const uint32_t* a,
                                         uint32_t b0, uint32_t b1) {
    asm volatile(
        "mma.sync.aligned.m16n8k16.row.col.f32.bf16.bf16.f32 "
        "{%0,%1,%2,%3}, {%4,%5,%6,%7}, {%8,%9}, {%0,%1,%2,%3};"
        : "+f"(c[0]), "+f"(c[1]), "+f"(c[2]), "+f"(c[3])
        : "r"(a[0]), "r"(a[1]), "r"(a[2]), "r"(a[3]), "r"(b0), "r"(b1));
}
__device__ __forceinline__ void cpa16(uint32_t dst, const void* src) {
    asm volatile("cp.async.cg.shared.global [%0], [%1], 16;" :: "r"(dst), "l"(src));
}

// ============================================================
// Kernel 1a: discretization + lambda^1024 via 10 complex squarings
// ============================================================
__global__ void prep_kernel(const float* __restrict__ log_dt,
                            const float* __restrict__ C,
                            const float* __restrict__ log_A_real,
                            const float* __restrict__ A_imag) {
    int idx = blockIdx.x*blockDim.x + threadIdx.x;
    if (idx >= Hh*N2d) return;
    int h = idx / N2d;
    float dt  = expf(log_dt[h]);
    float Are = -expf(log_A_real[idx]);
    float Aim = A_imag[idx];
    float dr = Are*dt, di = Aim*dt;
    float er = expf(dr);
    float lr = er*cosf(di), li = er*sinf(di);
    float e1r = lr - 1.0f, e1i = li;
    float den = Are*Are + Aim*Aim;
    float ir =  Are/den, ii = -Aim/den;
    float tr = e1r*ir - e1i*ii;
    float ti = e1r*ii + e1i*ir;
    float Cr = C[2*idx], Ci = C[2*idx+1];
    g_lam_re[idx] = lr;  g_lam_im[idx] = li;
    g_c_re[idx] = 2.0f*(Cr*tr - Ci*ti);
    g_c_im[idx] = 2.0f*(Cr*ti + Ci*tr);
    // lambda^1024 by repeated squaring (1024 = 2^10)
    float pr = lr, pi = li;
    #pragma unroll
    for (int s = 0; s < 10; ++s) {
        float nr = pr*pr - pi*pi;
        float ni = 2.0f*pr*pi;
        pr = nr; pi = ni;
    }
    g_lamK_re[idx] = pr; g_lamK_im[idx] = pi;
}

// ============================================================
// Kernel 1b: W -> bf16 hi/lo split
// ============================================================
__global__ void wsplit_kernel(const float* __restrict__ W) {
    int i = blockIdx.x*blockDim.x + threadIdx.x;
    if (i >= 2*Hh*Hh) return;
    float v = W[i];
    __nv_bfloat16 hi = __float2bfloat16(v);
    g_Whi[i] = hi;
    g_Wlo[i] = __float2bfloat16(v - __bfloat162float(hi));
}

// ============================================================
// Kernel 2a (scanA): chunk-local end states. warp = (b,h,chunk 0..2),
// lane = mode. t = lam*t + c*u over the chunk from t=0.
// ============================================================
__global__ void __launch_bounds__(256) scanA_kernel(const float* __restrict__ u) {
    int w    = threadIdx.x >> 5;
    int lane = threadIdx.x & 31;
    int wg   = blockIdx.x*8 + w;          // 0 .. 2048*3-1
    int bh   = wg / 3;
    int c    = wg - bh*3;
    int b    = bh >> 8;
    int h    = bh & 255;
    const float* up = u + (size_t)(b*Hh + h)*Ll + c*LCH;
    int ci = h*N2d + lane;
    float lr = g_lam_re[ci], li = g_lam_im[ci];
    float cr = g_c_re[ci],   cim = g_c_im[ci];
    float tre = 0.0f, tim = 0.0f;
    for (int g = 0; g < LCH/32; ++g) {
        float uv = up[g*32 + lane];
        #pragma unroll
        for (int i = 0; i < 32; ++i) {
            float ul = __shfl_sync(0xffffffffu, uv, i);
            float pr = tre, pi = tim;
            tre = fmaf(lr, pr, fmaf(-li, pi, cr*ul));
            tim = fmaf(lr, pi, fmaf( li, pr, cim*ul));
        }
    }
    g_S_re[(bh*3 + c)*N2d + lane] = tre;
    g_S_im[(bh*3 + c)*N2d + lane] = tim;
}

// ============================================================
// Kernel 2b (scanB): chain chunk states. warp = (b,h), lane = mode.
// Tend(c) = lamK*Tend(c-1) + S_c ; Tinit(c+1) = Tend(c).
// ============================================================
__global__ void __launch_bounds__(256) scanB_kernel() {
    int w    = threadIdx.x >> 5;
    int lane = threadIdx.x & 31;
    int bh   = blockIdx.x*8 + w;          // 0..2047
    int h    = bh & 255;
    int ci = h*N2d + lane;
    float kr = g_lamK_re[ci], ki = g_lamK_im[ci];
    float Tr = 0.0f, Ti = 0.0f;
    #pragma unroll
    for (int c = 0; c < 3; ++c) {
        float Sr = g_S_re[(bh*3 + c)*N2d + lane];
        float Si = g_S_im[(bh*3 + c)*N2d + lane];
        float nr = fmaf(kr, Tr, fmaf(-ki, Ti, Sr));
        float ni = fmaf(kr, Ti, fmaf( ki, Tr, Si));
        Tr = nr; Ti = ni;
        g_Ti_re[(bh*NCH + c + 1)*N2d + lane] = Tr;
        g_Ti_im[(bh*NCH + c + 1)*N2d + lane] = Ti;
    }
}

// ============================================================
// Kernel 2c (scanC): full scan per chunk from exact initial state,
// with mode reduction + skip + exact GELU + bf16 hi/lo output.
// warp = (b,h,chunk 0..3), lane = mode.
// ============================================================
__global__ void __launch_bounds__(256) scanC_kernel(const float* __restrict__ u,
                                                    const float* __restrict__ D) {
    __shared__ float tile[8][32][33];
    int w    = threadIdx.x >> 5;
    int lane = threadIdx.x & 31;
    int wg   = blockIdx.x*8 + w;          // 0 .. 2048*4-1
    int bh   = wg >> 2;
    int c    = wg & 3;
    int b    = bh >> 8;
    int h    = bh & 255;
    const float* up = u + (size_t)(b*Hh + h)*Ll + c*LCH;
    __nv_bfloat16* yh = g_Yhi + (size_t)(b*Hh + h)*Ll + c*LCH;
    __nv_bfloat16* yl = g_Ylo + (size_t)(b*Hh + h)*Ll + c*LCH;
    int ci = h*N2d + lane;
    float lr = g_lam_re[ci], li = g_lam_im[ci];
    float cr = g_c_re[ci],   cim = g_c_im[ci];
    float Dh = D[h];
    float tre = 0.0f, tim = 0.0f;
    if (c > 0) {
        tre = g_Ti_re[(bh*NCH + c)*N2d + lane];
        tim = g_Ti_im[(bh*NCH + c)*N2d + lane];
    }
    for (int g = 0; g < LCH/32; ++g) {
        float uv = up[g*32 + lane];
        #pragma unroll
        for (int i = 0; i < 32; ++i) {
            float ul = __shfl_sync(0xffffffffu, uv, i);
            float pr = tre, pi = tim;
            tre = fmaf(lr, pr, fmaf(-li, pi, cr*ul));
            tim = fmaf(lr, pi, fmaf( li, pr, cim*ul));
            tile[w][i][lane] = tre;   // [step i][mode lane]
        }
        __syncwarp();
        float acc = 0.0f;
        #pragma unroll
        for (int j = 0; j < 32; ++j) acc += tile[w][lane][j];
        float y = fmaf(Dh, uv, acc);
        float gl = 0.5f*y*(1.0f + erff(y*0.70710678118654752f));  // exact GELU
        __nv_bfloat16 hi = __float2bfloat16(gl);
        __nv_bfloat16 lo = __float2bfloat16(gl - __bfloat162float(hi));
        yh[g*32 + lane] = hi;
        yl[g*32 + lane] = lo;
        __syncwarp();
    }
}

// ============================================================
// Kernel 3: HMMA.16816 bf16-split GEMM + bias + GLU.
// CTA: 512 threads, 128 h-rows ('a' AND 'g') x 128 l-cols, K=256.
// 16 warps = 4(M) x 4(N), warp tile 32x32 per half (acc 64 regs).
// 3-stage cp.async pipeline.
// ============================================================
#define AROW 48
#define ABUF (128*AROW)              // 6144B per A array
#define BROW 272
#define BBUF (16*BROW)               // 4352B per B array
#define BOFF (4*ABUF)
#define STAGEB (4*ABUF + 2*BBUF)     // 33280B
#define GEMM_SMEM (3*STAGEB)         // 99840B

__global__ void __launch_bounds__(512, 1) gemm_mma_kernel(const float* __restrict__ bias,
                                                          float* __restrict__ out) {
    extern __shared__ char smem[];
    const uint32_t sb = smem_u32(smem);

    const int tid  = threadIdx.x;
    const int lane = tid & 31;
    const int w    = tid >> 5;
    const int wm   = w >> 2;          // 0..3  (32-row group)
    const int wn   = w & 3;           // 0..3  (32-col group)
    const int l0 = blockIdx.x*128;
    const int h0 = blockIdx.y*128;
    const int b  = blockIdx.z;

    // ---- cp.async mappings ----
    // A: arr = tid>>7 (0..3), row = tid&127; each thread copies 2x16B (full 32B k-row)
    const int aarr = tid >> 7, arow = tid & 127;
    const __nv_bfloat16* pA;
    {
        const __nv_bfloat16* bases[4];
        bases[0] = g_Whi + (size_t)(h0+arow)*Hh;
        bases[1] = g_Wlo + (size_t)(h0+arow)*Hh;
        bases[2] = g_Whi + (size_t)(Hh+h0+arow)*Hh;
        bases[3] = g_Wlo + (size_t)(Hh+h0+arow)*Hh;
        pA = bases[aarr];
    }
    const uint32_t aDst = (uint32_t)(aarr*ABUF + arow*AROW);
    // B: sel = tid>>8 (0=hi,1=lo), brow = (tid>>4)&15, bch = tid&15
    const int bsel = tid >> 8, brow = (tid >> 4) & 15, bch = tid & 15;
    const __nv_bfloat16* pB = (bsel ? g_Ylo : g_Yhi)
                            + ((size_t)b*Hh + brow)*Ll + l0 + bch*8;
    const uint32_t bDst = (uint32_t)(BOFF + bsel*BBUF + brow*BROW + bch*16);

    // ldmatrix lane addressing
    const uint32_t a_off = (uint32_t)((lane & 15)*AROW + (lane >> 4)*16);
    const uint32_t b_off = (uint32_t)(((lane & 7) + ((lane >> 3) & 1)*8)*BROW
                                      + (lane >> 4)*16);

    float acc_a[2][4][4], acc_g[2][4][4];
    #pragma unroll
    for (int i = 0; i < 2; ++i)
        #pragma unroll
        for (int j = 0; j < 4; ++j)
            #pragma unroll
            for (int q = 0; q < 4; ++q) { acc_a[i][j][q] = 0.f; acc_g[i][j][q] = 0.f; }

    // ---- pipeline prologue: stages 0,1 ----
    #pragma unroll
    for (int s = 0; s < 2; ++s) {
        uint32_t st = sb + (uint32_t)s*STAGEB;
        cpa16(st + aDst,      pA + s*16);
        cpa16(st + aDst + 16, pA + s*16 + 8);
        cpa16(st + bDst,      pB + (size_t)s*16*Ll);
        asm volatile("cp.async.commit_group;" ::: "memory");
    }

    int cur_s = 0;
    #pragma unroll 1
    for (int ks = 0; ks < 16; ++ks) {
        if (ks < 15) asm volatile("cp.async.wait_group 1;" ::: "memory");
        else         asm volatile("cp.async.wait_group 0;" ::: "memory");
        __syncthreads();
        if (ks + 2 < 16) {
            int s = ks + 2;
            int ss = cur_s + 2; if (ss >= 3) ss -= 3;
            uint32_t st = sb + (uint32_t)ss*STAGEB;
            cpa16(st + aDst,      pA + s*16);
            cpa16(st + aDst + 16, pA + s*16 + 8);
            cpa16(st + bDst,      pB + (size_t)s*16*Ll);
            asm volatile("cp.async.commit_group;" ::: "memory");
        }
        const uint32_t cur = sb + (uint32_t)cur_s*STAGEB;

        // ---- B fragments via ldmatrix.trans: 4 n8-blocks (32 cols) ----
        uint32_t bh[8], bl[8];
        {
            uint32_t bas_h = cur + BOFF + b_off + (uint32_t)(wn*64);
            uint32_t bas_l = bas_h + BBUF;
            ldsm4t(&bh[0], bas_h);
            ldsm4t(&bh[4], bas_h + 32);
            ldsm4t(&bl[0], bas_l);
            ldsm4t(&bl[4], bas_l + 32);
        }
        #pragma unroll
        for (int i = 0; i < 2; ++i) {
            uint32_t moff = (uint32_t)(wm*32 + i*16)*AROW + a_off;
            uint32_t ah[4], al[4];
            ldsm4(ah, cur + 0*ABUF + moff);
            ldsm4(al, cur + 1*ABUF + moff);
            #pragma unroll
            for (int j = 0; j < 4; ++j) {
                mma16816(acc_a[i][j], ah, bh[2*j], bh[2*j+1]);
                mma16816(acc_a[i][j], ah, bl[2*j], bl[2*j+1]);
                mma16816(acc_a[i][j], al, bh[2*j], bh[2*j+1]);
            }
            ldsm4(ah, cur + 2*ABUF + moff);
            ldsm4(al, cur + 3*ABUF + moff);
            #pragma unroll
            for (int j = 0; j < 4; ++j) {
                mma16816(acc_g[i][j], ah, bh[2*j], bh[2*j+1]);
                mma16816(acc_g[i][j], ah, bl[2*j], bl[2*j+1]);
                mma16816(acc_g[i][j], al, bh[2*j], bh[2*j+1]);
            }
        }
        if (++cur_s == 3) cur_s = 0;
    }

    // ---- epilogue: bias + GLU, in-register ----
    #pragma unroll
    for (int i = 0; i < 2; ++i) {
        int hr = h0 + wm*32 + i*16 + (lane >> 2);
        float ba0 = bias[hr],     bg0 = bias[Hh + hr];
        float ba1 = bias[hr + 8], bg1 = bias[Hh + hr + 8];
        #pragma unroll
        for (int j = 0; j < 4; ++j) {
            int col = l0 + wn*32 + j*8 + (lane & 3)*2;
            float a0 = acc_a[i][j][0] + ba0, g0 = acc_g[i][j][0] + bg0;
            float a1 = acc_a[i][j][1] + ba0, g1 = acc_g[i][j][1] + bg0;
            float a2 = acc_a[i][j][2] + ba1, g2 = acc_g[i][j][2] + bg1;
            float a3 = acc_a[i][j][3] + ba1, g3 = acc_g[i][j][3] + bg1;
            float2 v0 = make_float2(a0 / (1.0f + expf(-g0)),
                                    a1 / (1.0f + expf(-g1)));
            float2 v1 = make_float2(a2 / (1.0f + expf(-g2)),
                                    a3 / (1.0f + expf(-g3)));
            *(float2*)(out + ((size_t)b*Hh + hr)*Ll + col)     = v0;
            *(float2*)(out + ((size_t)b*Hh + hr + 8)*Ll + col) = v1;
        }
    }
}

// ============================================================
extern "C" void kernel_launch(void* const* d_in, const int* in_sizes, int n_in,
                              void* d_out, int out_size) {
    const float* u       = (const float*)d_in[0];
    const float* log_dt  = (const float*)d_in[1];
    const float* C       = (const float*)d_in[2];
    const float* lar     = (const float*)d_in[3];
    const float* aim     = (const float*)d_in[4];
    const float* D       = (const float*)d_in[5];
    const float* Wm      = (const float*)d_in[6];
    const float* bias    = (const float*)d_in[7];
    float* out = (float*)d_out;

    cudaFuncSetAttribute(gemm_mma_kernel,
                         cudaFuncAttributeMaxDynamicSharedMemorySize, GEMM_SMEM);

    prep_kernel<<<(Hh*N2d + 255)/256, 256>>>(log_dt, C, lar, aim);
    wsplit_kernel<<<(2*Hh*Hh + 255)/256, 256>>>(Wm);
    scanA_kernel<<<(Bb*Hh*3)/8, 256>>>(u);
    scanB_kernel<<<(Bb*Hh)/8, 256>>>();
    scanC_kernel<<<(Bb*Hh*NCH)/8, 256>>>(u, D);
    dim3 grid(Ll/128, Hh/128, Bb);
    gemm_mma_kernel<<<grid, 512, GEMM_SMEM>>>(bias, out);
}

// round 8
// speedup vs baseline: 1.0135x; 1.0135x over previous
#include <cuda_runtime.h>
#include <cuda_bf16.h>
#include <math.h>
#include <stdint.h>

#define Hh 256
#define N2d 32
#define Bb 8
#define Ll 4096
#define NCH 4                 // chunks per (b,h)
#define LCH (Ll/NCH)          // 1024

// -------- scratch (no allocations allowed) --------
__device__ float g_lam_re[Hh*N2d], g_lam_im[Hh*N2d];
__device__ float g_lamK_re[Hh*N2d], g_lamK_im[Hh*N2d];   // lambda^1024
__device__ float g_c_re[Hh*N2d],   g_c_im[Hh*N2d];
__device__ float g_S_re[Bb*Hh*3*N2d], g_S_im[Bb*Hh*3*N2d];       // chunk-local end states
__device__ float g_Ti_re[Bb*Hh*NCH*N2d], g_Ti_im[Bb*Hh*NCH*N2d]; // chunk initial states
__device__ __align__(16) __nv_bfloat16 g_Whi[2*Hh*Hh], g_Wlo[2*Hh*Hh];
// Y natural layout: [b][h][l]. hi/lo bf16 split of post-GELU activations.
__device__ __align__(16) __nv_bfloat16 g_Yhi[(size_t)Bb*Hh*Ll];
__device__ __align__(16) __nv_bfloat16 g_Ylo[(size_t)Bb*Hh*Ll];

__device__ __forceinline__ uint32_t smem_u32(const void* p) {
    uint32_t a;
    asm("{ .reg .u64 t; cvta.to.shared.u64 t, %1; cvt.u32.u64 %0, t; }" : "=r"(a) : "l"(p));
    return a;
}
__device__ __forceinline__ void ldsm4(uint32_t* r, uint32_t a) {
    asm volatile("ldmatrix.sync.aligned.m8n8.x4.shared.b16 {%0,%1,%2,%3}, [%4];"
                 : "=r"(r[0]), "=r"(r[1]), "=r"(r[2]), "=r"(r[3]) : "r"(a));
}
__device__ __forceinline__ void ldsm4t(uint32_t* r, uint32_t a) {
    asm volatile("ldmatrix.sync.aligned.m8n8.x4.trans.shared.b16 {%0,%1,%2,%3}, [%4];"
                 : "=r"(r[0]), "=r"(r[1]), "=r"(r[2]), "=r"(r[3]) : "r"(a));
}
__device__ __forceinline__ void mma16816(float* c, const uint32_t* a,
                                         uint32_t b0, uint32_t b1) {
    asm volatile(
        "mma.sync.aligned.m16n8k16.row.col.f32.bf16.bf16.f32 "
        "{%0,%1,%2,%3}, {%4,%5,%6,%7}, {%8,%9}, {%0,%1,%2,%3};"
        : "+f"(c[0]), "+f"(c[1]), "+f"(c[2]), "+f"(c[3])
        : "r"(a[0]), "r"(a[1]), "r"(a[2]), "r"(a[3]), "r"(b0), "r"(b1));
}
__device__ __forceinline__ void cpa16(uint32_t dst, const void* src) {
    asm volatile("cp.async.cg.shared.global [%0], [%1], 16;" :: "r"(dst), "l"(src));
}

// ============================================================
// Kernel 1a: discretization + lambda^1024 via 10 complex squarings
// ============================================================
__global__ void prep_kernel(const float* __restrict__ log_dt,
                            const float* __restrict__ C,
                            const float* __restrict__ log_A_real,
                            const float* __restrict__ A_imag) {
    int idx = blockIdx.x*blockDim.x + threadIdx.x;
    if (idx >= Hh*N2d) return;
    int h = idx / N2d;
    float dt  = expf(log_dt[h]);
    float Are = -expf(log_A_real[idx]);
    float Aim = A_imag[idx];
    float dr = Are*dt, di = Aim*dt;
    float er = expf(dr);
    float lr = er*cosf(di), li = er*sinf(di);
    float e1r = lr - 1.0f, e1i = li;
    float den = Are*Are + Aim*Aim;
    float ir =  Are/den, ii = -Aim/den;
    float tr = e1r*ir - e1i*ii;
    float ti = e1r*ii + e1i*ir;
    float Cr = C[2*idx], Ci = C[2*idx+1];
    g_lam_re[idx] = lr;  g_lam_im[idx] = li;
    g_c_re[idx] = 2.0f*(Cr*tr - Ci*ti);
    g_c_im[idx] = 2.0f*(Cr*ti + Ci*tr);
    // lambda^1024 by repeated squaring (1024 = 2^10)
    float pr = lr, pi = li;
    #pragma unroll
    for (int s = 0; s < 10; ++s) {
        float nr = pr*pr - pi*pi;
        float ni = 2.0f*pr*pi;
        pr = nr; pi = ni;
    }
    g_lamK_re[idx] = pr; g_lamK_im[idx] = pi;
}

// ============================================================
// Kernel 1b: W -> bf16 hi/lo split
// ============================================================
__global__ void wsplit_kernel(const float* __restrict__ W) {
    int i = blockIdx.x*blockDim.x + threadIdx.x;
    if (i >= 2*Hh*Hh) return;
    float v = W[i];
    __nv_bfloat16 hi = __float2bfloat16(v);
    g_Whi[i] = hi;
    g_Wlo[i] = __float2bfloat16(v - __bfloat162float(hi));
}

// ============================================================
// Kernel 2a (scanA): chunk-local end states. warp = (b,h,chunk 0..2),
// lane = mode. t = lam*t + c*u over the chunk from t=0.
// ============================================================
__global__ void __launch_bounds__(256) scanA_kernel(const float* __restrict__ u) {
    int w    = threadIdx.x >> 5;
    int lane = threadIdx.x & 31;
    int wg   = blockIdx.x*8 + w;          // 0 .. 2048*3-1
    int bh   = wg / 3;
    int c    = wg - bh*3;
    int b    = bh >> 8;
    int h    = bh & 255;
    const float* up = u + (size_t)(b*Hh + h)*Ll + c*LCH;
    int ci = h*N2d + lane;
    float lr = g_lam_re[ci], li = g_lam_im[ci];
    float cr = g_c_re[ci],   cim = g_c_im[ci];
    float tre = 0.0f, tim = 0.0f;
    for (int g = 0; g < LCH/32; ++g) {
        float uv = up[g*32 + lane];
        #pragma unroll
        for (int i = 0; i < 32; ++i) {
            float ul = __shfl_sync(0xffffffffu, uv, i);
            float pr = tre, pi = tim;
            tre = fmaf(lr, pr, fmaf(-li, pi, cr*ul));
            tim = fmaf(lr, pi, fmaf( li, pr, cim*ul));
        }
    }
    g_S_re[(bh*3 + c)*N2d + lane] = tre;
    g_S_im[(bh*3 + c)*N2d + lane] = tim;
}

// ============================================================
// Kernel 2b (scanB): chain chunk states. warp = (b,h), lane = mode.
// ============================================================
__global__ void __launch_bounds__(256) scanB_kernel() {
    int w    = threadIdx.x >> 5;
    int lane = threadIdx.x & 31;
    int bh   = blockIdx.x*8 + w;          // 0..2047
    int h    = bh & 255;
    int ci = h*N2d + lane;
    float kr = g_lamK_re[ci], ki = g_lamK_im[ci];
    float Tr = 0.0f, Ti = 0.0f;
    #pragma unroll
    for (int c = 0; c < 3; ++c) {
        float Sr = g_S_re[(bh*3 + c)*N2d + lane];
        float Si = g_S_im[(bh*3 + c)*N2d + lane];
        float nr = fmaf(kr, Tr, fmaf(-ki, Ti, Sr));
        float ni = fmaf(kr, Ti, fmaf( ki, Tr, Si));
        Tr = nr; Ti = ni;
        g_Ti_re[(bh*NCH + c + 1)*N2d + lane] = Tr;
        g_Ti_im[(bh*NCH + c + 1)*N2d + lane] = Ti;
    }
}

// ============================================================
// Kernel 2c (scanC): full scan per chunk from exact initial state,
// with mode reduction + skip + exact GELU + bf16 hi/lo output.
// ============================================================
__global__ void __launch_bounds__(256) scanC_kernel(const float* __restrict__ u,
                                                    const float* __restrict__ D) {
    __shared__ float tile[8][32][33];
    int w    = threadIdx.x >> 5;
    int lane = threadIdx.x & 31;
    int wg   = blockIdx.x*8 + w;          // 0 .. 2048*4-1
    int bh   = wg >> 2;
    int c    = wg & 3;
    int b    = bh >> 8;
    int h    = bh & 255;
    const float* up = u + (size_t)(b*Hh + h)*Ll + c*LCH;
    __nv_bfloat16* yh = g_Yhi + (size_t)(b*Hh + h)*Ll + c*LCH;
    __nv_bfloat16* yl = g_Ylo + (size_t)(b*Hh + h)*Ll + c*LCH;
    int ci = h*N2d + lane;
    float lr = g_lam_re[ci], li = g_lam_im[ci];
    float cr = g_c_re[ci],   cim = g_c_im[ci];
    float Dh = D[h];
    float tre = 0.0f, tim = 0.0f;
    if (c > 0) {
        tre = g_Ti_re[(bh*NCH + c)*N2d + lane];
        tim = g_Ti_im[(bh*NCH + c)*N2d + lane];
    }
    for (int g = 0; g < LCH/32; ++g) {
        float uv = up[g*32 + lane];
        #pragma unroll
        for (int i = 0; i < 32; ++i) {
            float ul = __shfl_sync(0xffffffffu, uv, i);
            float pr = tre, pi = tim;
            tre = fmaf(lr, pr, fmaf(-li, pi, cr*ul));
            tim = fmaf(lr, pi, fmaf( li, pr, cim*ul));
            tile[w][i][lane] = tre;   // [step i][mode lane]
        }
        __syncwarp();
        float acc = 0.0f;
        #pragma unroll
        for (int j = 0; j < 32; ++j) acc += tile[w][lane][j];
        float y = fmaf(Dh, uv, acc);
        float gl = 0.5f*y*(1.0f + erff(y*0.70710678118654752f));  // exact GELU
        __nv_bfloat16 hi = __float2bfloat16(gl);
        __nv_bfloat16 lo = __float2bfloat16(gl - __bfloat162float(hi));
        yh[g*32 + lane] = hi;
        yl[g*32 + lane] = lo;
        __syncwarp();
    }
}

// ============================================================
// Kernel 3: HMMA.16816 bf16-split GEMM + bias + GLU (R6 version,
// measured 109us). 256 threads, 128x128 tile, 3-stage cp.async.
// ============================================================
#define AROW 48
#define ABUF (128*AROW)              // 6144B per A array
#define BROW 272
#define BBUF (16*BROW)               // 4352B per B array
#define BOFF (4*ABUF)
#define STAGEB (4*ABUF + 2*BBUF)     // 33280B
#define GEMM_SMEM (3*STAGEB)         // 99840B

__global__ void __launch_bounds__(256, 1) gemm_mma_kernel(const float* __restrict__ bias,
                                                          float* __restrict__ out) {
    extern __shared__ char smem[];
    const uint32_t sb = smem_u32(smem);

    const int tid  = threadIdx.x;
    const int lane = tid & 31;
    const int w    = tid >> 5;
    const int wm   = w >> 2;          // 0..1  (64-row group)
    const int wn   = w & 3;           // 0..3  (32-col group)
    const int l0 = blockIdx.x*128;
    const int h0 = blockIdx.y*128;
    const int b  = blockIdx.z;

    // A: row = tid>>1 (0..127), chunk = tid&1 (16B each of 32B row)
    const int arow = tid >> 1, ach = tid & 1;
    const __nv_bfloat16* pA[4];
    pA[0] = g_Whi + (size_t)(h0+arow)*Hh      + ach*8;
    pA[1] = g_Wlo + (size_t)(h0+arow)*Hh      + ach*8;
    pA[2] = g_Whi + (size_t)(Hh+h0+arow)*Hh   + ach*8;
    pA[3] = g_Wlo + (size_t)(Hh+h0+arow)*Hh   + ach*8;
    const uint32_t aDst = (uint32_t)(arow*AROW + ach*16);
    // B: row = tid>>4 (0..15 = k within step), chunk = tid&15 (16B of 256B row)
    const int brow = tid >> 4, bch = tid & 15;
    const __nv_bfloat16* pBh = g_Yhi + ((size_t)b*Hh + brow)*Ll + l0 + bch*8;
    const __nv_bfloat16* pBl = g_Ylo + ((size_t)b*Hh + brow)*Ll + l0 + bch*8;
    const uint32_t bDst = (uint32_t)(brow*BROW + bch*16);

    const uint32_t a_off = (uint32_t)((lane & 15)*AROW + (lane >> 4)*16);
    const uint32_t b_off = (uint32_t)(((lane & 7) + ((lane >> 3) & 1)*8)*BROW
                                      + (lane >> 4)*16);

    float acc_a[4][4][4], acc_g[4][4][4];
    #pragma unroll
    for (int i = 0; i < 4; ++i)
        #pragma unroll
        for (int j = 0; j < 4; ++j)
            #pragma unroll
            for (int q = 0; q < 4; ++q) { acc_a[i][j][q] = 0.f; acc_g[i][j][q] = 0.f; }

    #pragma unroll
    for (int s = 0; s < 2; ++s) {
        uint32_t st = sb + (uint32_t)s*STAGEB;
        #pragma unroll
        for (int t = 0; t < 4; ++t)
            cpa16(st + t*ABUF + aDst, pA[t] + s*16);
        cpa16(st + BOFF + bDst,        pBh + (size_t)s*16*Ll);
        cpa16(st + BOFF + BBUF + bDst, pBl + (size_t)s*16*Ll);
        asm volatile("cp.async.commit_group;" ::: "memory");
    }

    int cur_s = 0;
    #pragma unroll 1
    for (int ks = 0; ks < 16; ++ks) {
        if (ks < 15) asm volatile("cp.async.wait_group 1;" ::: "memory");
        else         asm volatile("cp.async.wait_group 0;" ::: "memory");
        __syncthreads();
        if (ks + 2 < 16) {
            int s = ks + 2;
            int ss = cur_s + 2; if (ss >= 3) ss -= 3;
            uint32_t st = sb + (uint32_t)ss*STAGEB;
            #pragma unroll
            for (int t = 0; t < 4; ++t)
                cpa16(st + t*ABUF + aDst, pA[t] + s*16);
            cpa16(st + BOFF + bDst,        pBh + (size_t)s*16*Ll);
            cpa16(st + BOFF + BBUF + bDst, pBl + (size_t)s*16*Ll);
            asm volatile("cp.async.commit_group;" ::: "memory");
        }
        const uint32_t cur = sb + (uint32_t)cur_s*STAGEB;

        uint32_t bh[8], bl[8];
        {
            uint32_t bas_h = cur + BOFF + b_off + (uint32_t)(wn*64);
            uint32_t bas_l = bas_h + BBUF;
            ldsm4t(&bh[0], bas_h);
            ldsm4t(&bh[4], bas_h + 32);
            ldsm4t(&bl[0], bas_l);
            ldsm4t(&bl[4], bas_l + 32);
        }
        #pragma unroll
        for (int i = 0; i < 4; ++i) {
            uint32_t moff = (uint32_t)(wm*64 + i*16)*AROW + a_off;
            uint32_t ah[4], al[4];
            ldsm4(ah, cur + 0*ABUF + moff);
            ldsm4(al, cur + 1*ABUF + moff);
            #pragma unroll
            for (int j = 0; j < 4; ++j) {
                mma16816(acc_a[i][j], ah, bh[2*j], bh[2*j+1]);
                mma16816(acc_a[i][j], ah, bl[2*j], bl[2*j+1]);
                mma16816(acc_a[i][j], al, bh[2*j], bh[2*j+1]);
            }
            ldsm4(ah, cur + 2*ABUF + moff);
            ldsm4(al, cur + 3*ABUF + moff);
            #pragma unroll
            for (int j = 0; j < 4; ++j) {
                mma16816(acc_g[i][j], ah, bh[2*j], bh[2*j+1]);
                mma16816(acc_g[i][j], ah, bl[2*j], bl[2*j+1]);
                mma16816(acc_g[i][j], al, bh[2*j], bh[2*j+1]);
            }
        }
        if (++cur_s == 3) cur_s = 0;
    }

    #pragma unroll
    for (int i = 0; i < 4; ++i) {
        int hr = h0 + wm*64 + i*16 + (lane >> 2);
        float ba0 = bias[hr],     bg0 = bias[Hh + hr];
        float ba1 = bias[hr + 8], bg1 = bias[Hh + hr + 8];
        #pragma unroll
        for (int j = 0; j < 4; ++j) {
            int col = l0 + wn*32 + j*8 + (lane & 3)*2;
            float a0 = acc_a[i][j][0] + ba0, g0 = acc_g[i][j][0] + bg0;
            float a1 = acc_a[i][j][1] + ba0, g1 = acc_g[i][j][1] + bg0;
            float a2 = acc_a[i][j][2] + ba1, g2 = acc_g[i][j][2] + bg1;
            float a3 = acc_a[i][j][3] + ba1, g3 = acc_g[i][j][3] + bg1;
            float2 v0 = make_float2(a0 / (1.0f + expf(-g0)),
                                    a1 / (1.0f + expf(-g1)));
            float2 v1 = make_float2(a2 / (1.0f + expf(-g2)),
                                    a3 / (1.0f + expf(-g3)));
            *(float2*)(out + ((size_t)b*Hh + hr)*Ll + col)     = v0;
            *(float2*)(out + ((size_t)b*Hh + hr + 8)*Ll + col) = v1;
        }
    }
}

// ============================================================
extern "C" void kernel_launch(void* const* d_in, const int* in_sizes, int n_in,
                              void* d_out, int out_size) {
    const float* u       = (const float*)d_in[0];
    const float* log_dt  = (const float*)d_in[1];
    const float* C       = (const float*)d_in[2];
    const float* lar     = (const float*)d_in[3];
    const float* aim     = (const float*)d_in[4];
    const float* D       = (const float*)d_in[5];
    const float* Wm      = (const float*)d_in[6];
    const float* bias    = (const float*)d_in[7];
    float* out = (float*)d_out;

    cudaFuncSetAttribute(gemm_mma_kernel,
                         cudaFuncAttributeMaxDynamicSharedMemorySize, GEMM_SMEM);

    prep_kernel<<<(Hh*N2d + 255)/256, 256>>>(log_dt, C, lar, aim);
    wsplit_kernel<<<(2*Hh*Hh + 255)/256, 256>>>(Wm);
    scanA_kernel<<<(Bb*Hh*3)/8, 256>>>(u);
    scanB_kernel<<<(Bb*Hh)/8, 256>>>();
    scanC_kernel<<<(Bb*Hh*NCH)/8, 256>>>(u, D);
    dim3 grid(Ll/128, Hh/128, Bb);
    gemm_mma_kernel<<<grid, 256, GEMM_SMEM>>>(bias, out);
}

// round 9
// speedup vs baseline: 1.2016x; 1.1856x over previous
#include <cuda_runtime.h>
#include <cuda_bf16.h>
#include <math.h>
#include <stdint.h>

#define Hh 256
#define N2d 32
#define Bb 8
#define Ll 4096

// -------- scratch (no allocations allowed) --------
__device__ float g_lam_re[Hh*N2d], g_lam_im[Hh*N2d];
__device__ float g_c_re[Hh*N2d],   g_c_im[Hh*N2d];
__device__ __align__(16) __nv_bfloat16 g_Whi[2*Hh*Hh], g_Wlo[2*Hh*Hh];
// Y natural layout: [b][h][l]. hi/lo bf16 split of post-GELU activations.
__device__ __align__(16) __nv_bfloat16 g_Yhi[(size_t)Bb*Hh*Ll];
__device__ __align__(16) __nv_bfloat16 g_Ylo[(size_t)Bb*Hh*Ll];

__device__ __forceinline__ uint32_t smem_u32(const void* p) {
    uint32_t a;
    asm("{ .reg .u64 t; cvta.to.shared.u64 t, %1; cvt.u32.u64 %0, t; }" : "=r"(a) : "l"(p));
    return a;
}
__device__ __forceinline__ void ldsm4(uint32_t* r, uint32_t a) {
    asm volatile("ldmatrix.sync.aligned.m8n8.x4.shared.b16 {%0,%1,%2,%3}, [%4];"
                 : "=r"(r[0]), "=r"(r[1]), "=r"(r[2]), "=r"(r[3]) : "r"(a));
}
__device__ __forceinline__ void ldsm4t(uint32_t* r, uint32_t a) {
    asm volatile("ldmatrix.sync.aligned.m8n8.x4.trans.shared.b16 {%0,%1,%2,%3}, [%4];"
                 : "=r"(r[0]), "=r"(r[1]), "=r"(r[2]), "=r"(r[3]) : "r"(a));
}
__device__ __forceinline__ void mma16816(float* c, const uint32_t* a,
                                         uint32_t b0, uint32_t b1) {
    asm volatile(
        "mma.sync.aligned.m16n8k16.row.col.f32.bf16.bf16.f32 "
        "{%0,%1,%2,%3}, {%4,%5,%6,%7}, {%8,%9}, {%0,%1,%2,%3};"
        : "+f"(c[0]), "+f"(c[1]), "+f"(c[2]), "+f"(c[3])
        : "r"(a[0]), "r"(a[1]), "r"(a[2]), "r"(a[3]), "r"(b0), "r"(b1));
}
__device__ __forceinline__ void cpa16(uint32_t dst, const void* src) {
    asm volatile("cp.async.cg.shared.global [%0], [%1], 16;" :: "r"(dst), "l"(src));
}

// ============================================================
// Kernel 1a: discretization  lambda = exp(dt*A),  c = 2*C*(lambda-1)/A
// ============================================================
__global__ void prep_kernel(const float* __restrict__ log_dt,
                            const float* __restrict__ C,
                            const float* __restrict__ log_A_real,
                            const float* __restrict__ A_imag) {
    int idx = blockIdx.x*blockDim.x + threadIdx.x;
    if (idx >= Hh*N2d) return;
    int h = idx / N2d;
    float dt  = expf(log_dt[h]);
    float Are = -expf(log_A_real[idx]);
    float Aim = A_imag[idx];
    float dr = Are*dt, di = Aim*dt;
    float er = expf(dr);
    float lr = er*cosf(di), li = er*sinf(di);
    float e1r = lr - 1.0f, e1i = li;
    float den = Are*Are + Aim*Aim;
    float ir =  Are/den, ii = -Aim/den;
    float tr = e1r*ir - e1i*ii;
    float ti = e1r*ii + e1i*ir;
    float Cr = C[2*idx], Ci = C[2*idx+1];
    g_lam_re[idx] = lr;  g_lam_im[idx] = li;
    g_c_re[idx] = 2.0f*(Cr*tr - Ci*ti);
    g_c_im[idx] = 2.0f*(Cr*ti + Ci*tr);
}

// ============================================================
// Kernel 1b: W -> bf16 hi/lo split
// ============================================================
__global__ void wsplit_kernel(const float* __restrict__ W) {
    int i = blockIdx.x*blockDim.x + threadIdx.x;
    if (i >= 2*Hh*Hh) return;
    float v = W[i];
    __nv_bfloat16 hi = __float2bfloat16(v);
    g_Whi[i] = hi;
    g_Wlo[i] = __float2bfloat16(v - __bfloat162float(hi));
}

// ============================================================
// Kernel 2: monolithic diagonal-SSM scan. One warp per (b,h),
// lane = mode n. Structural-stall fixes:
//  - u for block ch+1 prefetched into a register before block ch's
//    recurrence (hides L2/DRAM latency behind 32 steps of math)
//  - mode reduction uses 4 interleaved accumulators (breaks the
//    32-deep serial FADD chain)
// ============================================================
__global__ void __launch_bounds__(256) scan_kernel(const float* __restrict__ u,
                                                   const float* __restrict__ D) {
    __shared__ float tile[8][32][33];
    int w    = threadIdx.x >> 5;
    int lane = threadIdx.x & 31;
    int wg   = blockIdx.x*8 + w;          // 0..2047
    int b    = wg >> 8;
    int h    = wg & 255;
    const float* up = u + (size_t)(b*Hh + h)*Ll;
    __nv_bfloat16* yh = g_Yhi + (size_t)(b*Hh + h)*Ll;
    __nv_bfloat16* yl = g_Ylo + (size_t)(b*Hh + h)*Ll;
    int ci = h*N2d + lane;
    float lr = g_lam_re[ci], li = g_lam_im[ci];
    float cr = g_c_re[ci],   cim = g_c_im[ci];
    float Dh = D[h];
    float tre = 0.0f, tim = 0.0f;

    float uv = up[lane];                  // block 0
    for (int ch = 0; ch < Ll/32; ++ch) {
        // prefetch next block's u (register; clamped on last block)
        int nidx = (ch + 1 < Ll/32) ? (ch + 1)*32 : ch*32;
        float uv_next = up[nidx + lane];
        #pragma unroll
        for (int i = 0; i < 32; ++i) {
            float ul = __shfl_sync(0xffffffffu, uv, i);
            float pr = tre, pi = tim;
            tre = fmaf(lr, pr, fmaf(-li, pi, cr*ul));
            tim = fmaf(lr, pi, fmaf( li, pr, cim*ul));
            tile[w][i][lane] = tre;   // [step i][mode lane]
        }
        __syncwarp();
        // lane = output step: sum over modes with 4 accumulators
        float a0 = 0.f, a1 = 0.f, a2 = 0.f, a3 = 0.f;
        #pragma unroll
        for (int j = 0; j < 32; j += 4) {
            a0 += tile[w][lane][j+0];
            a1 += tile[w][lane][j+1];
            a2 += tile[w][lane][j+2];
            a3 += tile[w][lane][j+3];
        }
        float acc = (a0 + a1) + (a2 + a3);
        float y = fmaf(Dh, uv, acc);
        float gl = 0.5f*y*(1.0f + erff(y*0.70710678118654752f));  // exact GELU
        __nv_bfloat16 hi = __float2bfloat16(gl);
        __nv_bfloat16 lo = __float2bfloat16(gl - __bfloat162float(hi));
        yh[ch*32 + lane] = hi;
        yl[ch*32 + lane] = lo;
        uv = uv_next;
        __syncwarp();
    }
}

// ============================================================
// Kernel 3: HMMA.16816 bf16-split GEMM + bias + GLU (R6 version,
// measured 109us — near the mma.sync rate floor).
// ============================================================
#define AROW 48
#define ABUF (128*AROW)              // 6144B per A array
#define BROW 272
#define BBUF (16*BROW)               // 4352B per B array
#define BOFF (4*ABUF)
#define STAGEB (4*ABUF + 2*BBUF)     // 33280B
#define GEMM_SMEM (3*STAGEB)         // 99840B

__global__ void __launch_bounds__(256, 1) gemm_mma_kernel(const float* __restrict__ bias,
                                                          float* __restrict__ out) {
    extern __shared__ char smem[];
    const uint32_t sb = smem_u32(smem);

    const int tid  = threadIdx.x;
    const int lane = tid & 31;
    const int w    = tid >> 5;
    const int wm   = w >> 2;          // 0..1  (64-row group)
    const int wn   = w & 3;           // 0..3  (32-col group)
    const int l0 = blockIdx.x*128;
    const int h0 = blockIdx.y*128;
    const int b  = blockIdx.z;

    const int arow = tid >> 1, ach = tid & 1;
    const __nv_bfloat16* pA[4];
    pA[0] = g_Whi + (size_t)(h0+arow)*Hh      + ach*8;
    pA[1] = g_Wlo + (size_t)(h0+arow)*Hh      + ach*8;
    pA[2] = g_Whi + (size_t)(Hh+h0+arow)*Hh   + ach*8;
    pA[3] = g_Wlo + (size_t)(Hh+h0+arow)*Hh   + ach*8;
    const uint32_t aDst = (uint32_t)(arow*AROW + ach*16);
    const int brow = tid >> 4, bch = tid & 15;
    const __nv_bfloat16* pBh = g_Yhi + ((size_t)b*Hh + brow)*Ll + l0 + bch*8;
    const __nv_bfloat16* pBl = g_Ylo + ((size_t)b*Hh + brow)*Ll + l0 + bch*8;
    const uint32_t bDst = (uint32_t)(brow*BROW + bch*16);

    const uint32_t a_off = (uint32_t)((lane & 15)*AROW + (lane >> 4)*16);
    const uint32_t b_off = (uint32_t)(((lane & 7) + ((lane >> 3) & 1)*8)*BROW
                                      + (lane >> 4)*16);

    float acc_a[4][4][4], acc_g[4][4][4];
    #pragma unroll
    for (int i = 0; i < 4; ++i)
        #pragma unroll
        for (int j = 0; j < 4; ++j)
            #pragma unroll
            for (int q = 0; q < 4; ++q) { acc_a[i][j][q] = 0.f; acc_g[i][j][q] = 0.f; }

    #pragma unroll
    for (int s = 0; s < 2; ++s) {
        uint32_t st = sb + (uint32_t)s*STAGEB;
        #pragma unroll
        for (int t = 0; t < 4; ++t)
            cpa16(st + t*ABUF + aDst, pA[t] + s*16);
        cpa16(st + BOFF + bDst,        pBh + (size_t)s*16*Ll);
        cpa16(st + BOFF + BBUF + bDst, pBl + (size_t)s*16*Ll);
        asm volatile("cp.async.commit_group;" ::: "memory");
    }

    int cur_s = 0;
    #pragma unroll 1
    for (int ks = 0; ks < 16; ++ks) {
        if (ks < 15) asm volatile("cp.async.wait_group 1;" ::: "memory");
        else         asm volatile("cp.async.wait_group 0;" ::: "memory");
        __syncthreads();
        if (ks + 2 < 16) {
            int s = ks + 2;
            int ss = cur_s + 2; if (ss >= 3) ss -= 3;
            uint32_t st = sb + (uint32_t)ss*STAGEB;
            #pragma unroll
            for (int t = 0; t < 4; ++t)
                cpa16(st + t*ABUF + aDst, pA[t] + s*16);
            cpa16(st + BOFF + bDst,        pBh + (size_t)s*16*Ll);
            cpa16(st + BOFF + BBUF + bDst, pBl + (size_t)s*16*Ll);
            asm volatile("cp.async.commit_group;" ::: "memory");
        }
        const uint32_t cur = sb + (uint32_t)cur_s*STAGEB;

        uint32_t bh[8], bl[8];
        {
            uint32_t bas_h = cur + BOFF + b_off + (uint32_t)(wn*64);
            uint32_t bas_l = bas_h + BBUF;
            ldsm4t(&bh[0], bas_h);
            ldsm4t(&bh[4], bas_h + 32);
            ldsm4t(&bl[0], bas_l);
            ldsm4t(&bl[4], bas_l + 32);
        }
        #pragma unroll
        for (int i = 0; i < 4; ++i) {
            uint32_t moff = (uint32_t)(wm*64 + i*16)*AROW + a_off;
            uint32_t ah[4], al[4];
            ldsm4(ah, cur + 0*ABUF + moff);
            ldsm4(al, cur + 1*ABUF + moff);
            #pragma unroll
            for (int j = 0; j < 4; ++j) {
                mma16816(acc_a[i][j], ah, bh[2*j], bh[2*j+1]);
                mma16816(acc_a[i][j], ah, bl[2*j], bl[2*j+1]);
                mma16816(acc_a[i][j], al, bh[2*j], bh[2*j+1]);
            }
            ldsm4(ah, cur + 2*ABUF + moff);
            ldsm4(al, cur + 3*ABUF + moff);
            #pragma unroll
            for (int j = 0; j < 4; ++j) {
                mma16816(acc_g[i][j], ah, bh[2*j], bh[2*j+1]);
                mma16816(acc_g[i][j], ah, bl[2*j], bl[2*j+1]);
                mma16816(acc_g[i][j], al, bh[2*j], bh[2*j+1]);
            }
        }
        if (++cur_s == 3) cur_s = 0;
    }

    #pragma unroll
    for (int i = 0; i < 4; ++i) {
        int hr = h0 + wm*64 + i*16 + (lane >> 2);
        float ba0 = bias[hr],     bg0 = bias[Hh + hr];
        float ba1 = bias[hr + 8], bg1 = bias[Hh + hr + 8];
        #pragma unroll
        for (int j = 0; j < 4; ++j) {
            int col = l0 + wn*32 + j*8 + (lane & 3)*2;
            float a0 = acc_a[i][j][0] + ba0, g0 = acc_g[i][j][0] + bg0;
            float a1 = acc_a[i][j][1] + ba0, g1 = acc_g[i][j][1] + bg0;
            float a2 = acc_a[i][j][2] + ba1, g2 = acc_g[i][j][2] + bg1;
            float a3 = acc_a[i][j][3] + ba1, g3 = acc_g[i][j][3] + bg1;
            float2 v0 = make_float2(a0 / (1.0f + expf(-g0)),
                                    a1 / (1.0f + expf(-g1)));
            float2 v1 = make_float2(a2 / (1.0f + expf(-g2)),
                                    a3 / (1.0f + expf(-g3)));
            *(float2*)(out + ((size_t)b*Hh + hr)*Ll + col)     = v0;
            *(float2*)(out + ((size_t)b*Hh + hr + 8)*Ll + col) = v1;
        }
    }
}

// ============================================================
extern "C" void kernel_launch(void* const* d_in, const int* in_sizes, int n_in,
                              void* d_out, int out_size) {
    const float* u       = (const float*)d_in[0];
    const float* log_dt  = (const float*)d_in[1];
    const float* C       = (const float*)d_in[2];
    const float* lar     = (const float*)d_in[3];
    const float* aim     = (const float*)d_in[4];
    const float* D       = (const float*)d_in[5];
    const float* Wm      = (const float*)d_in[6];
    const float* bias    = (const float*)d_in[7];
    float* out = (float*)d_out;

    cudaFuncSetAttribute(gemm_mma_kernel,
                         cudaFuncAttributeMaxDynamicSharedMemorySize, GEMM_SMEM);

    prep_kernel<<<(Hh*N2d + 255)/256, 256>>>(log_dt, C, lar, aim);
    wsplit_kernel<<<(2*Hh*Hh + 255)/256, 256>>>(Wm);
    scan_kernel<<<(Bb*Hh)/8, 256>>>(u, D);
    dim3 grid(Ll/128, Hh/128, Bb);
    gemm_mma_kernel<<<grid, 256, GEMM_SMEM>>>(bias, out);
}

// round 10
// speedup vs baseline: 1.3275x; 1.1048x over previous
#include <cuda_runtime.h>
#include <cuda_fp16.h>
#include <math.h>
#include <stdint.h>

#define Hh 256
#define N2d 32
#define Bb 8
#define Ll 4096

// -------- scratch (no allocations allowed) --------
__device__ float g_lam_re[Hh*N2d], g_lam_im[Hh*N2d];
__device__ float g_c_re[Hh*N2d],   g_c_im[Hh*N2d];
__device__ __align__(16) __half g_Whi[2*Hh*Hh], g_Wlo[2*Hh*Hh];
// Y natural layout: [b][h][l]. single fp16 (post-GELU activations).
__device__ __align__(16) __half g_Yh[(size_t)Bb*Hh*Ll];

__device__ __forceinline__ uint32_t smem_u32(const void* p) {
    uint32_t a;
    asm("{ .reg .u64 t; cvta.to.shared.u64 t, %1; cvt.u32.u64 %0, t; }" : "=r"(a) : "l"(p));
    return a;
}
__device__ __forceinline__ void ldsm4(uint32_t* r, uint32_t a) {
    asm volatile("ldmatrix.sync.aligned.m8n8.x4.shared.b16 {%0,%1,%2,%3}, [%4];"
                 : "=r"(r[0]), "=r"(r[1]), "=r"(r[2]), "=r"(r[3]) : "r"(a));
}
__device__ __forceinline__ void ldsm4t(uint32_t* r, uint32_t a) {
    asm volatile("ldmatrix.sync.aligned.m8n8.x4.trans.shared.b16 {%0,%1,%2,%3}, [%4];"
                 : "=r"(r[0]), "=r"(r[1]), "=r"(r[2]), "=r"(r[3]) : "r"(a));
}
__device__ __forceinline__ void mma16816(float* c, const uint32_t* a,
                                         uint32_t b0, uint32_t b1) {
    asm volatile(
        "mma.sync.aligned.m16n8k16.row.col.f32.f16.f16.f32 "
        "{%0,%1,%2,%3}, {%4,%5,%6,%7}, {%8,%9}, {%0,%1,%2,%3};"
        : "+f"(c[0]), "+f"(c[1]), "+f"(c[2]), "+f"(c[3])
        : "r"(a[0]), "r"(a[1]), "r"(a[2]), "r"(a[3]), "r"(b0), "r"(b1));
}
__device__ __forceinline__ void cpa16(uint32_t dst, const void* src) {
    asm volatile("cp.async.cg.shared.global [%0], [%1], 16;" :: "r"(dst), "l"(src));
}

// ============================================================
// Kernel 1a: discretization  lambda = exp(dt*A),  c = 2*C*(lambda-1)/A
// ============================================================
__global__ void prep_kernel(const float* __restrict__ log_dt,
                            const float* __restrict__ C,
                            const float* __restrict__ log_A_real,
                            const float* __restrict__ A_imag) {
    int idx = blockIdx.x*blockDim.x + threadIdx.x;
    if (idx >= Hh*N2d) return;
    int h = idx / N2d;
    float dt  = expf(log_dt[h]);
    float Are = -expf(log_A_real[idx]);
    float Aim = A_imag[idx];
    float dr = Are*dt, di = Aim*dt;
    float er = expf(dr);
    float lr = er*cosf(di), li = er*sinf(di);
    float e1r = lr - 1.0f, e1i = li;
    float den = Are*Are + Aim*Aim;
    float ir =  Are/den, ii = -Aim/den;
    float tr = e1r*ir - e1i*ii;
    float ti = e1r*ii + e1i*ir;
    float Cr = C[2*idx], Ci = C[2*idx+1];
    g_lam_re[idx] = lr;  g_lam_im[idx] = li;
    g_c_re[idx] = 2.0f*(Cr*tr - Ci*ti);
    g_c_im[idx] = 2.0f*(Cr*ti + Ci*tr);
}

// ============================================================
// Kernel 1b: W -> fp16 hi/lo split (W = Whi + Wlo exact to ~2^-22)
// ============================================================
__global__ void wsplit_kernel(const float* __restrict__ W) {
    int i = blockIdx.x*blockDim.x + threadIdx.x;
    if (i >= 2*Hh*Hh) return;
    float v = W[i];
    __half hi = __float2half(v);
    g_Whi[i] = hi;
    g_Wlo[i] = __float2half(v - __half2float(hi));
}

// ============================================================
// Kernel 2: monolithic diagonal-SSM scan. One warp per (b,h),
// lane = mode n. u prefetch + 4-way split reduction. Single fp16
// Y output (no lo split).
// ============================================================
__global__ void __launch_bounds__(256) scan_kernel(const float* __restrict__ u,
                                                   const float* __restrict__ D) {
    __shared__ float tile[8][32][33];
    int w    = threadIdx.x >> 5;
    int lane = threadIdx.x & 31;
    int wg   = blockIdx.x*8 + w;          // 0..2047
    int b    = wg >> 8;
    int h    = wg & 255;
    const float* up = u + (size_t)(b*Hh + h)*Ll;
    __half* yh = g_Yh + (size_t)(b*Hh + h)*Ll;
    int ci = h*N2d + lane;
    float lr = g_lam_re[ci], li = g_lam_im[ci];
    float cr = g_c_re[ci],   cim = g_c_im[ci];
    float Dh = D[h];
    float tre = 0.0f, tim = 0.0f;

    float uv = up[lane];                  // block 0
    for (int ch = 0; ch < Ll/32; ++ch) {
        int nidx = (ch + 1 < Ll/32) ? (ch + 1)*32 : ch*32;
        float uv_next = up[nidx + lane];
        #pragma unroll
        for (int i = 0; i < 32; ++i) {
            float ul = __shfl_sync(0xffffffffu, uv, i);
            float pr = tre, pi = tim;
            tre = fmaf(lr, pr, fmaf(-li, pi, cr*ul));
            tim = fmaf(lr, pi, fmaf( li, pr, cim*ul));
            tile[w][i][lane] = tre;   // [step i][mode lane]
        }
        __syncwarp();
        float a0 = 0.f, a1 = 0.f, a2 = 0.f, a3 = 0.f;
        #pragma unroll
        for (int j = 0; j < 32; j += 4) {
            a0 += tile[w][lane][j+0];
            a1 += tile[w][lane][j+1];
            a2 += tile[w][lane][j+2];
            a3 += tile[w][lane][j+3];
        }
        float acc = (a0 + a1) + (a2 + a3);
        float y = fmaf(Dh, uv, acc);
        float gl = 0.5f*y*(1.0f + erff(y*0.70710678118654752f));  // exact GELU
        yh[ch*32 + lane] = __float2half(gl);
        uv = uv_next;
        __syncwarp();
    }
}

// ============================================================
// Kernel 3: HMMA.16816 fp16 2-term GEMM + bias + GLU.
// z = (Whi + Wlo) @ Yh. 256 threads, 128x128 tile, K=256,
// 3-stage cp.async pipeline. 64 MMAs/warp/ks (was 96).
// ============================================================
#define AROW 48
#define ABUF (128*AROW)              // 6144B per A array
#define BROW 272
#define BBUF (16*BROW)               // 4352B (single B array)
#define BOFF (4*ABUF)
#define STAGEB (4*ABUF + BBUF)       // 28928B
#define GEMM_SMEM (3*STAGEB)         // 86784B

__global__ void __launch_bounds__(256, 1) gemm_mma_kernel(const float* __restrict__ bias,
                                                          float* __restrict__ out) {
    extern __shared__ char smem[];
    const uint32_t sb = smem_u32(smem);

    const int tid  = threadIdx.x;
    const int lane = tid & 31;
    const int w    = tid >> 5;
    const int wm   = w >> 2;          // 0..1  (64-row group)
    const int wn   = w & 3;           // 0..3  (32-col group)
    const int l0 = blockIdx.x*128;
    const int h0 = blockIdx.y*128;
    const int b  = blockIdx.z;

    // A: row = tid>>1 (0..127), chunk = tid&1 (16B each of 32B row)
    const int arow = tid >> 1, ach = tid & 1;
    const __half* pA[4];
    pA[0] = g_Whi + (size_t)(h0+arow)*Hh      + ach*8;
    pA[1] = g_Wlo + (size_t)(h0+arow)*Hh      + ach*8;
    pA[2] = g_Whi + (size_t)(Hh+h0+arow)*Hh   + ach*8;
    pA[3] = g_Wlo + (size_t)(Hh+h0+arow)*Hh   + ach*8;
    const uint32_t aDst = (uint32_t)(arow*AROW + ach*16);
    // B: row = tid>>4 (0..15 = k within step), chunk = tid&15 (16B of 256B row)
    const int brow = tid >> 4, bch = tid & 15;
    const __half* pB = g_Yh + ((size_t)b*Hh + brow)*Ll + l0 + bch*8;
    const uint32_t bDst = (uint32_t)(BOFF + brow*BROW + bch*16);

    const uint32_t a_off = (uint32_t)((lane & 15)*AROW + (lane >> 4)*16);
    const uint32_t b_off = (uint32_t)(((lane & 7) + ((lane >> 3) & 1)*8)*BROW
                                      + (lane >> 4)*16);

    float acc_a[4][4][4], acc_g[4][4][4];
    #pragma unroll
    for (int i = 0; i < 4; ++i)
        #pragma unroll
        for (int j = 0; j < 4; ++j)
            #pragma unroll
            for (int q = 0; q < 4; ++q) { acc_a[i][j][q] = 0.f; acc_g[i][j][q] = 0.f; }

    #pragma unroll
    for (int s = 0; s < 2; ++s) {
        uint32_t st = sb + (uint32_t)s*STAGEB;
        #pragma unroll
        for (int t = 0; t < 4; ++t)
            cpa16(st + t*ABUF + aDst, pA[t] + s*16);
        cpa16(st + bDst, pB + (size_t)s*16*Ll);
        asm volatile("cp.async.commit_group;" ::: "memory");
    }

    int cur_s = 0;
    #pragma unroll 1
    for (int ks = 0; ks < 16; ++ks) {
        if (ks < 15) asm volatile("cp.async.wait_group 1;" ::: "memory");
        else         asm volatile("cp.async.wait_group 0;" ::: "memory");
        __syncthreads();
        if (ks + 2 < 16) {
            int s = ks + 2;
            int ss = cur_s + 2; if (ss >= 3) ss -= 3;
            uint32_t st = sb + (uint32_t)ss*STAGEB;
            #pragma unroll
            for (int t = 0; t < 4; ++t)
                cpa16(st + t*ABUF + aDst, pA[t] + s*16);
            cpa16(st + bDst, pB + (size_t)s*16*Ll);
            asm volatile("cp.async.commit_group;" ::: "memory");
        }
        const uint32_t cur = sb + (uint32_t)cur_s*STAGEB;

        // ---- B fragments via ldmatrix.trans: 4 n8-blocks ----
        uint32_t bh[8];
        {
            uint32_t bas = cur + BOFF + b_off + (uint32_t)(wn*64);
            ldsm4t(&bh[0], bas);
            ldsm4t(&bh[4], bas + 32);
        }
        #pragma unroll
        for (int i = 0; i < 4; ++i) {
            uint32_t moff = (uint32_t)(wm*64 + i*16)*AROW + a_off;
            uint32_t ah[4], al[4];
            ldsm4(ah, cur + 0*ABUF + moff);
            ldsm4(al, cur + 1*ABUF + moff);
            #pragma unroll
            for (int j = 0; j < 4; ++j) {
                mma16816(acc_a[i][j], ah, bh[2*j], bh[2*j+1]);
                mma16816(acc_a[i][j], al, bh[2*j], bh[2*j+1]);
            }
            ldsm4(ah, cur + 2*ABUF + moff);
            ldsm4(al, cur + 3*ABUF + moff);
            #pragma unroll
            for (int j = 0; j < 4; ++j) {
                mma16816(acc_g[i][j], ah, bh[2*j], bh[2*j+1]);
                mma16816(acc_g[i][j], al, bh[2*j], bh[2*j+1]);
            }
        }
        if (++cur_s == 3) cur_s = 0;
    }

    // ---- epilogue: bias + GLU, in-register ----
    #pragma unroll
    for (int i = 0; i < 4; ++i) {
        int hr = h0 + wm*64 + i*16 + (lane >> 2);
        float ba0 = bias[hr],     bg0 = bias[Hh + hr];
        float ba1 = bias[hr + 8], bg1 = bias[Hh + hr + 8];
        #pragma unroll
        for (int j = 0; j < 4; ++j) {
            int col = l0 + wn*32 + j*8 + (lane & 3)*2;
            float a0 = acc_a[i][j][0] + ba0, g0 = acc_g[i][j][0] + bg0;
            float a1 = acc_a[i][j][1] + ba0, g1 = acc_g[i][j][1] + bg0;
            float a2 = acc_a[i][j][2] + ba1, g2 = acc_g[i][j][2] + bg1;
            float a3 = acc_a[i][j][3] + ba1, g3 = acc_g[i][j][3] + bg1;
            float2 v0 = make_float2(a0 / (1.0f + expf(-g0)),
                                    a1 / (1.0f + expf(-g1)));
            float2 v1 = make_float2(a2 / (1.0f + expf(-g2)),
                                    a3 / (1.0f + expf(-g3)));
            *(float2*)(out + ((size_t)b*Hh + hr)*Ll + col)     = v0;
            *(float2*)(out + ((size_t)b*Hh + hr + 8)*Ll + col) = v1;
        }
    }
}

// ============================================================
extern "C" void kernel_launch(void* const* d_in, const int* in_sizes, int n_in,
                              void* d_out, int out_size) {
    const float* u       = (const float*)d_in[0];
    const float* log_dt  = (const float*)d_in[1];
    const float* C       = (const float*)d_in[2];
    const float* lar     = (const float*)d_in[3];
    const float* aim     = (const float*)d_in[4];
    const float* D       = (const float*)d_in[5];
    const float* Wm      = (const float*)d_in[6];
    const float* bias    = (const float*)d_in[7];
    float* out = (float*)d_out;

    cudaFuncSetAttribute(gemm_mma_kernel,
                         cudaFuncAttributeMaxDynamicSharedMemorySize, GEMM_SMEM);

    prep_kernel<<<(Hh*N2d + 255)/256, 256>>>(log_dt, C, lar, aim);
    wsplit_kernel<<<(2*Hh*Hh + 255)/256, 256>>>(Wm);
    scan_kernel<<<(Bb*Hh)/8, 256>>>(u, D);
    dim3 grid(Ll/128, Hh/128, Bb);
    gemm_mma_kernel<<<grid, 256, GEMM_SMEM>>>(bias, out);
}

// round 11
// speedup vs baseline: 1.6121x; 1.2144x over previous
#include <cuda_runtime.h>
#include <cuda_fp16.h>
#include <math.h>
#include <stdint.h>

#define Hh 256
#define N2d 32
#define Bb 8
#define Ll 4096

typedef unsigned long long ull;

// -------- scratch (no allocations allowed) --------
__device__ float g_lam_re[Hh*N2d], g_lam_im[Hh*N2d];
__device__ float g_c_re[Hh*N2d],   g_c_im[Hh*N2d];
__device__ __align__(16) __half g_Wh[2*Hh*Hh];
// Y natural layout: [b][h][l]. single fp16 (post-GELU activations).
__device__ __align__(16) __half g_Yh[(size_t)Bb*Hh*Ll];

__device__ __forceinline__ uint32_t smem_u32(const void* p) {
    uint32_t a;
    asm("{ .reg .u64 t; cvta.to.shared.u64 t, %1; cvt.u32.u64 %0, t; }" : "=r"(a) : "l"(p));
    return a;
}
__device__ __forceinline__ void ldsm4(uint32_t* r, uint32_t a) {
    asm volatile("ldmatrix.sync.aligned.m8n8.x4.shared.b16 {%0,%1,%2,%3}, [%4];"
                 : "=r"(r[0]), "=r"(r[1]), "=r"(r[2]), "=r"(r[3]) : "r"(a));
}
__device__ __forceinline__ void ldsm4t(uint32_t* r, uint32_t a) {
    asm volatile("ldmatrix.sync.aligned.m8n8.x4.trans.shared.b16 {%0,%1,%2,%3}, [%4];"
                 : "=r"(r[0]), "=r"(r[1]), "=r"(r[2]), "=r"(r[3]) : "r"(a));
}
__device__ __forceinline__ void mma16816(float* c, const uint32_t* a,
                                         uint32_t b0, uint32_t b1) {
    asm volatile(
        "mma.sync.aligned.m16n8k16.row.col.f32.f16.f16.f32 "
        "{%0,%1,%2,%3}, {%4,%5,%6,%7}, {%8,%9}, {%0,%1,%2,%3};"
        : "+f"(c[0]), "+f"(c[1]), "+f"(c[2]), "+f"(c[3])
        : "r"(a[0]), "r"(a[1]), "r"(a[2]), "r"(a[3]), "r"(b0), "r"(b1));
}
__device__ __forceinline__ void cpa16(uint32_t dst, const void* src) {
    asm volatile("cp.async.cg.shared.global [%0], [%1], 16;" :: "r"(dst), "l"(src));
}
// ---- packed f32x2 helpers (sm_100+ base ISA; validated on this toolchain) ----
__device__ __forceinline__ ull pk2f(float lo, float hi) {
    ull r; asm("mov.b64 %0, {%1,%2};" : "=l"(r) : "f"(lo), "f"(hi)); return r;
}
__device__ __forceinline__ void upk2f(ull v, float& lo, float& hi) {
    asm("mov.b64 {%0,%1}, %2;" : "=f"(lo), "=f"(hi) : "l"(v));
}
__device__ __forceinline__ ull mul2(ull a, ull b) {
    ull d; asm("mul.rn.f32x2 %0, %1, %2;" : "=l"(d) : "l"(a), "l"(b)); return d;
}
__device__ __forceinline__ ull fma2(ull a, ull b, ull c) {
    ull d; asm("fma.rn.f32x2 %0, %1, %2, %3;" : "=l"(d) : "l"(a), "l"(b), "l"(c)); return d;
}
__device__ __forceinline__ ull add2(ull a, ull b) {
    ull d; asm("add.rn.f32x2 %0, %1, %2;" : "=l"(d) : "l"(a), "l"(b)); return d;
}

// ============================================================
// Kernel 1a: discretization  lambda = exp(dt*A),  c = 2*C*(lambda-1)/A
// ============================================================
__global__ void prep_kernel(const float* __restrict__ log_dt,
                            const float* __restrict__ C,
                            const float* __restrict__ log_A_real,
                            const float* __restrict__ A_imag) {
    int idx = blockIdx.x*blockDim.x + threadIdx.x;
    if (idx >= Hh*N2d) return;
    int h = idx / N2d;
    float dt  = expf(log_dt[h]);
    float Are = -expf(log_A_real[idx]);
    float Aim = A_imag[idx];
    float dr = Are*dt, di = Aim*dt;
    float er = expf(dr);
    float lr = er*cosf(di), li = er*sinf(di);
    float e1r = lr - 1.0f, e1i = li;
    float den = Are*Are + Aim*Aim;
    float ir =  Are/den, ii = -Aim/den;
    float tr = e1r*ir - e1i*ii;
    float ti = e1r*ii + e1i*ir;
    float Cr = C[2*idx], Ci = C[2*idx+1];
    g_lam_re[idx] = lr;  g_lam_im[idx] = li;
    g_c_re[idx] = 2.0f*(Cr*tr - Ci*ti);
    g_c_im[idx] = 2.0f*(Cr*ti + Ci*tr);
}

// ============================================================
// Kernel 1b: W -> fp16
// ============================================================
__global__ void wsplit_kernel(const float* __restrict__ W) {
    int i = blockIdx.x*blockDim.x + threadIdx.x;
    if (i >= 2*Hh*Hh) return;
    g_Wh[i] = __float2half(W[i]);
}

// ============================================================
// Kernel 2: monolithic diagonal-SSM scan, f32x2-packed recurrence.
// One warp per (b,h), lane = mode n.
//   T = (tre,tim);  T' = LR2*T + LI2*swap(T) + C2*(u,u)
// halves fma-pipe occupancy vs 6 scalar FFMAs.
// ============================================================
__global__ void __launch_bounds__(256) scan_kernel(const float* __restrict__ u,
                                                   const float* __restrict__ D) {
    __shared__ float tile[8][32][34];   // stride 34 -> 8B-aligned rows for LDS.64
    int w    = threadIdx.x >> 5;
    int lane = threadIdx.x & 31;
    int wg   = blockIdx.x*8 + w;          // 0..2047
    int b    = wg >> 8;
    int h    = wg & 255;
    const float* up = u + (size_t)(b*Hh + h)*Ll;
    __half* yh = g_Yh + (size_t)(b*Hh + h)*Ll;
    int ci = h*N2d + lane;
    float lr = g_lam_re[ci], li = g_lam_im[ci];
    float cr = g_c_re[ci],   cim = g_c_im[ci];
    float Dh = D[h];
    const ull LR2 = pk2f(lr, lr);
    const ull LI2 = pk2f(-li, li);
    const ull C2  = pk2f(cr, cim);
    float tre = 0.0f, tim = 0.0f;

    float uv = up[lane];                  // block 0
    for (int ch = 0; ch < Ll/32; ++ch) {
        int nidx = (ch + 1 < Ll/32) ? (ch + 1)*32 : ch*32;
        float uv_next = up[nidx + lane];
        #pragma unroll
        for (int i = 0; i < 32; ++i) {
            float ul = __shfl_sync(0xffffffffu, uv, i);
            ull UU = pk2f(ul, ul);
            ull P  = mul2(C2, UU);                 // (cr*u, ci*u)
            ull T  = pk2f(tre, tim);
            ull TS = pk2f(tim, tre);
            ull Q  = fma2(LR2, T, P);              // (lr*tre+cr*u, lr*tim+ci*u)
            ull Tn = fma2(LI2, TS, Q);             // complete complex step
            upk2f(Tn, tre, tim);
            tile[w][i][lane] = tre;   // [step i][mode lane]
        }
        __syncwarp();
        // lane = output step: packed sum over modes
        const float* row = &tile[w][lane][0];
        ull s0 = 0ULL, s1 = 0ULL, s2 = 0ULL, s3 = 0ULL;   // (0.f,0.f)
        #pragma unroll
        for (int j = 0; j < 32; j += 8) {
            s0 = add2(s0, *(const ull*)(row + j + 0));
            s1 = add2(s1, *(const ull*)(row + j + 2));
            s2 = add2(s2, *(const ull*)(row + j + 4));
            s3 = add2(s3, *(const ull*)(row + j + 6));
        }
        ull st = add2(add2(s0, s1), add2(s2, s3));
        float alo, ahi; upk2f(st, alo, ahi);
        float acc = alo + ahi;
        float y = fmaf(Dh, uv, acc);
        float gl = 0.5f*y*(1.0f + erff(y*0.70710678118654752f));  // exact GELU
        yh[ch*32 + lane] = __float2half(gl);
        uv = uv_next;
        __syncwarp();
    }
}

// ============================================================
// Kernel 3: HMMA.16816 fp16 single-term GEMM + bias + GLU.
// z = Wh @ Yh. 256 threads, 128x128 tile, K=256, 3-stage cp.async.
// 32 MMAs/warp/ks.
// ============================================================
#define AROW 48
#define ABUF (128*AROW)              // 6144B per A array
#define BROW 272
#define BBUF (16*BROW)               // 4352B (single B array)
#define BOFF (2*ABUF)
#define STAGEB (2*ABUF + BBUF)       // 16640B
#define GEMM_SMEM (3*STAGEB)         // 49920B

__global__ void __launch_bounds__(256, 1) gemm_mma_kernel(const float* __restrict__ bias,
                                                          float* __restrict__ out) {
    extern __shared__ char smem[];
    const uint32_t sb = smem_u32(smem);

    const int tid  = threadIdx.x;
    const int lane = tid & 31;
    const int w    = tid >> 5;
    const int wm   = w >> 2;          // 0..1  (64-row group)
    const int wn   = w & 3;           // 0..3  (32-col group)
    const int l0 = blockIdx.x*128;
    const int h0 = blockIdx.y*128;
    const int b  = blockIdx.z;

    // A: row = tid>>1 (0..127), chunk = tid&1 (16B each of 32B row)
    const int arow = tid >> 1, ach = tid & 1;
    const __half* pA[2];
    pA[0] = g_Wh + (size_t)(h0+arow)*Hh      + ach*8;
    pA[1] = g_Wh + (size_t)(Hh+h0+arow)*Hh   + ach*8;
    const uint32_t aDst = (uint32_t)(arow*AROW + ach*16);
    // B: row = tid>>4 (0..15 = k within step), chunk = tid&15 (16B of 256B row)
    const int brow = tid >> 4, bch = tid & 15;
    const __half* pB = g_Yh + ((size_t)b*Hh + brow)*Ll + l0 + bch*8;
    const uint32_t bDst = (uint32_t)(BOFF + brow*BROW + bch*16);

    const uint32_t a_off = (uint32_t)((lane & 15)*AROW + (lane >> 4)*16);
    const uint32_t b_off = (uint32_t)(((lane & 7) + ((lane >> 3) & 1)*8)*BROW
                                      + (lane >> 4)*16);

    float acc_a[4][4][4], acc_g[4][4][4];
    #pragma unroll
    for (int i = 0; i < 4; ++i)
        #pragma unroll
        for (int j = 0; j < 4; ++j)
            #pragma unroll
            for (int q = 0; q < 4; ++q) { acc_a[i][j][q] = 0.f; acc_g[i][j][q] = 0.f; }

    #pragma unroll
    for (int s = 0; s < 2; ++s) {
        uint32_t st = sb + (uint32_t)s*STAGEB;
        cpa16(st + 0*ABUF + aDst, pA[0] + s*16);
        cpa16(st + 1*ABUF + aDst, pA[1] + s*16);
        cpa16(st + bDst, pB + (size_t)s*16*Ll);
        asm volatile("cp.async.commit_group;" ::: "memory");
    }

    int cur_s = 0;
    #pragma unroll 1
    for (int ks = 0; ks < 16; ++ks) {
        if (ks < 15) asm volatile("cp.async.wait_group 1;" ::: "memory");
        else         asm volatile("cp.async.wait_group 0;" ::: "memory");
        __syncthreads();
        if (ks + 2 < 16) {
            int s = ks + 2;
            int ss = cur_s + 2; if (ss >= 3) ss -= 3;
            uint32_t st = sb + (uint32_t)ss*STAGEB;
            cpa16(st + 0*ABUF + aDst, pA[0] + s*16);
            cpa16(st + 1*ABUF + aDst, pA[1] + s*16);
            cpa16(st + bDst, pB + (size_t)s*16*Ll);
            asm volatile("cp.async.commit_group;" ::: "memory");
        }
        const uint32_t cur = sb + (uint32_t)cur_s*STAGEB;

        // ---- B fragments via ldmatrix.trans: 4 n8-blocks ----
        uint32_t bh[8];
        {
            uint32_t bas = cur + BOFF + b_off + (uint32_t)(wn*64);
            ldsm4t(&bh[0], bas);
            ldsm4t(&bh[4], bas + 32);
        }
        #pragma unroll
        for (int i = 0; i < 4; ++i) {
            uint32_t moff = (uint32_t)(wm*64 + i*16)*AROW + a_off;
            uint32_t aa[4], ag[4];
            ldsm4(aa, cur + 0*ABUF + moff);
            ldsm4(ag, cur + 1*ABUF + moff);
            #pragma unroll
            for (int j = 0; j < 4; ++j) {
                mma16816(acc_a[i][j], aa, bh[2*j], bh[2*j+1]);
                mma16816(acc_g[i][j], ag, bh[2*j], bh[2*j+1]);
            }
        }
        if (++cur_s == 3) cur_s = 0;
    }

    // ---- epilogue: bias + GLU, in-register ----
    #pragma unroll
    for (int i = 0; i < 4; ++i) {
        int hr = h0 + wm*64 + i*16 + (lane >> 2);
        float ba0 = bias[hr],     bg0 = bias[Hh + hr];
        float ba1 = bias[hr + 8], bg1 = bias[Hh + hr + 8];
        #pragma unroll
        for (int j = 0; j < 4; ++j) {
            int col = l0 + wn*32 + j*8 + (lane & 3)*2;
            float a0 = acc_a[i][j][0] + ba0, g0 = acc_g[i][j][0] + bg0;
            float a1 = acc_a[i][j][1] + ba0, g1 = acc_g[i][j][1] + bg0;
            float a2 = acc_a[i][j][2] + ba1, g2 = acc_g[i][j][2] + bg1;
            float a3 = acc_a[i][j][3] + ba1, g3 = acc_g[i][j][3] + bg1;
            float2 v0 = make_float2(a0 / (1.0f + expf(-g0)),
                                    a1 / (1.0f + expf(-g1)));
            float2 v1 = make_float2(a2 / (1.0f + expf(-g2)),
                                    a3 / (1.0f + expf(-g3)));
            *(float2*)(out + ((size_t)b*Hh + hr)*Ll + col)     = v0;
            *(float2*)(out + ((size_t)b*Hh + hr + 8)*Ll + col) = v1;
        }
    }
}

// ============================================================
extern "C" void kernel_launch(void* const* d_in, const int* in_sizes, int n_in,
                              void* d_out, int out_size) {
    const float* u       = (const float*)d_in[0];
    const float* log_dt  = (const float*)d_in[1];
    const float* C       = (const float*)d_in[2];
    const float* lar     = (const float*)d_in[3];
    const float* aim     = (const float*)d_in[4];
    const float* D       = (const float*)d_in[5];
    const float* Wm      = (const float*)d_in[6];
    const float* bias    = (const float*)d_in[7];
    float* out = (float*)d_out;

    cudaFuncSetAttribute(gemm_mma_kernel,
                         cudaFuncAttributeMaxDynamicSharedMemorySize, GEMM_SMEM);

    prep_kernel<<<(Hh*N2d + 255)/256, 256>>>(log_dt, C, lar, aim);
    wsplit_kernel<<<(2*Hh*Hh + 255)/256, 256>>>(Wm);
    scan_kernel<<<(Bb*Hh)/8, 256>>>(u, D);
    dim3 grid(Ll/128, Hh/128, Bb);
    gemm_mma_kernel<<<grid, 256, GEMM_SMEM>>>(bias, out);
}

// round 12
// speedup vs baseline: 1.7087x; 1.0600x over previous
#include <cuda_runtime.h>
#include <cuda_fp16.h>
#include <math.h>
#include <stdint.h>

#define Hh 256
#define N2d 32
#define Bb 8
#define Ll 4096

typedef unsigned long long ull;

// -------- scratch (no allocations allowed) --------
__device__ float g_lam_re[Hh*N2d], g_lam_im[Hh*N2d];
__device__ float g_c_re[Hh*N2d],   g_c_im[Hh*N2d];
__device__ __align__(16) __half g_Wh[2*Hh*Hh];
// Y natural layout: [b][h][l]. single fp16 (post-GELU activations).
__device__ __align__(16) __half g_Yh[(size_t)Bb*Hh*Ll];

__device__ __forceinline__ uint32_t smem_u32(const void* p) {
    uint32_t a;
    asm("{ .reg .u64 t; cvta.to.shared.u64 t, %1; cvt.u32.u64 %0, t; }" : "=r"(a) : "l"(p));
    return a;
}
__device__ __forceinline__ void ldsm4(uint32_t* r, uint32_t a) {
    asm volatile("ldmatrix.sync.aligned.m8n8.x4.shared.b16 {%0,%1,%2,%3}, [%4];"
                 : "=r"(r[0]), "=r"(r[1]), "=r"(r[2]), "=r"(r[3]) : "r"(a));
}
__device__ __forceinline__ void ldsm4t(uint32_t* r, uint32_t a) {
    asm volatile("ldmatrix.sync.aligned.m8n8.x4.trans.shared.b16 {%0,%1,%2,%3}, [%4];"
                 : "=r"(r[0]), "=r"(r[1]), "=r"(r[2]), "=r"(r[3]) : "r"(a));
}
__device__ __forceinline__ void mma16816(float* c, const uint32_t* a,
                                         uint32_t b0, uint32_t b1) {
    asm volatile(
        "mma.sync.aligned.m16n8k16.row.col.f32.f16.f16.f32 "
        "{%0,%1,%2,%3}, {%4,%5,%6,%7}, {%8,%9}, {%0,%1,%2,%3};"
        : "+f"(c[0]), "+f"(c[1]), "+f"(c[2]), "+f"(c[3])
        : "r"(a[0]), "r"(a[1]), "r"(a[2]), "r"(a[3]), "r"(b0), "r"(b1));
}
__device__ __forceinline__ void cpa16(uint32_t dst, const void* src) {
    asm volatile("cp.async.cg.shared.global [%0], [%1], 16;" :: "r"(dst), "l"(src));
}
// ---- packed f32x2 helpers ----
__device__ __forceinline__ ull pk2f(float lo, float hi) {
    ull r; asm("mov.b64 %0, {%1,%2};" : "=l"(r) : "f"(lo), "f"(hi)); return r;
}
__device__ __forceinline__ void upk2f(ull v, float& lo, float& hi) {
    asm("mov.b64 {%0,%1}, %2;" : "=f"(lo), "=f"(hi) : "l"(v));
}
__device__ __forceinline__ ull mul2(ull a, ull b) {
    ull d; asm("mul.rn.f32x2 %0, %1, %2;" : "=l"(d) : "l"(a), "l"(b)); return d;
}
__device__ __forceinline__ ull fma2(ull a, ull b, ull c) {
    ull d; asm("fma.rn.f32x2 %0, %1, %2, %3;" : "=l"(d) : "l"(a), "l"(b), "l"(c)); return d;
}
__device__ __forceinline__ ull add2(ull a, ull b) {
    ull d; asm("add.rn.f32x2 %0, %1, %2;" : "=l"(d) : "l"(a), "l"(b)); return d;
}

// ============================================================
// Kernel 1a: discretization  lambda = exp(dt*A),  c = 2*C*(lambda-1)/A
// ============================================================
__global__ void prep_kernel(const float* __restrict__ log_dt,
                            const float* __restrict__ C,
                            const float* __restrict__ log_A_real,
                            const float* __restrict__ A_imag) {
    int idx = blockIdx.x*blockDim.x + threadIdx.x;
    if (idx >= Hh*N2d) return;
    int h = idx / N2d;
    float dt  = expf(log_dt[h]);
    float Are = -expf(log_A_real[idx]);
    float Aim = A_imag[idx];
    float dr = Are*dt, di = Aim*dt;
    float er = expf(dr);
    float lr = er*cosf(di), li = er*sinf(di);
    float e1r = lr - 1.0f, e1i = li;
    float den = Are*Are + Aim*Aim;
    float ir =  Are/den, ii = -Aim/den;
    float tr = e1r*ir - e1i*ii;
    float ti = e1r*ii + e1i*ir;
    float Cr = C[2*idx], Ci = C[2*idx+1];
    g_lam_re[idx] = lr;  g_lam_im[idx] = li;
    g_c_re[idx] = 2.0f*(Cr*tr - Ci*ti);
    g_c_im[idx] = 2.0f*(Cr*ti + Ci*tr);
}

// ============================================================
// Kernel 1b: W -> fp16
// ============================================================
__global__ void wsplit_kernel(const float* __restrict__ W) {
    int i = blockIdx.x*blockDim.x + threadIdx.x;
    if (i >= 2*Hh*Hh) return;
    g_Wh[i] = __float2half(W[i]);
}

// ============================================================
// Kernel 2: monolithic diagonal-SSM scan, f32x2-packed recurrence
// with PERMANENTLY packed state (swap = 2 movs; no per-step
// pack/unpack of T). One warp per (b,h), lane = mode n.
// ============================================================
__global__ void __launch_bounds__(256) scan_kernel(const float* __restrict__ u,
                                                   const float* __restrict__ D) {
    __shared__ float tile[8][32][34];
    int w    = threadIdx.x >> 5;
    int lane = threadIdx.x & 31;
    int wg   = blockIdx.x*8 + w;          // 0..2047
    int b    = wg >> 8;
    int h    = wg & 255;
    const float* up = u + (size_t)(b*Hh + h)*Ll;
    __half* yh = g_Yh + (size_t)(b*Hh + h)*Ll;
    int ci = h*N2d + lane;
    float lr = g_lam_re[ci], li = g_lam_im[ci];
    float cr = g_c_re[ci],   cim = g_c_im[ci];
    float Dh = D[h];
    const ull LR2 = pk2f(lr, lr);
    const ull LI2 = pk2f(-li, li);
    const ull C2  = pk2f(cr, cim);
    ull TP = 0ULL;                        // packed (tre, tim) = (0,0)

    float uv = up[lane];                  // block 0
    for (int ch = 0; ch < Ll/32; ++ch) {
        int nidx = (ch + 1 < Ll/32) ? (ch + 1)*32 : ch*32;
        float uv_next = up[nidx + lane];
        #pragma unroll
        for (int i = 0; i < 32; ++i) {
            float ul = __shfl_sync(0xffffffffu, uv, i);
            ull UU = pk2f(ul, ul);
            ull P  = mul2(C2, UU);                 // (cr*u, ci*u)
            float tlo, thi; upk2f(TP, tlo, thi);   // reg aliases
            ull TS = pk2f(thi, tlo);               // swapped pair (2 movs)
            ull Q  = fma2(LR2, TP, P);
            TP = fma2(LI2, TS, Q);
            float nlo, nhi; upk2f(TP, nlo, nhi);
            tile[w][i][lane] = nlo;                // store tre only
        }
        __syncwarp();
        // lane = output step: packed sum over modes
        const float* row = &tile[w][lane][0];
        ull s0 = 0ULL, s1 = 0ULL, s2 = 0ULL, s3 = 0ULL;
        #pragma unroll
        for (int j = 0; j < 32; j += 8) {
            s0 = add2(s0, *(const ull*)(row + j + 0));
            s1 = add2(s1, *(const ull*)(row + j + 2));
            s2 = add2(s2, *(const ull*)(row + j + 4));
            s3 = add2(s3, *(const ull*)(row + j + 6));
        }
        ull st = add2(add2(s0, s1), add2(s2, s3));
        float alo, ahi; upk2f(st, alo, ahi);
        float acc = alo + ahi;
        float y = fmaf(Dh, uv, acc);
        float gl = 0.5f*y*(1.0f + erff(y*0.70710678118654752f));  // exact GELU
        yh[ch*32 + lane] = __float2half(gl);
        uv = uv_next;
        __syncwarp();
    }
}

// ============================================================
// Kernel 3: HMMA.16816 fp16 GEMM + bias + GLU. 512 threads,
// 128x128 tile, 16 warps = 4(M) x 4(N), warp tile 32x32 per half.
// 3-stage cp.async. 4 warps/SMSP for latency hiding.
// ============================================================
#define AROW 48
#define ABUF (128*AROW)              // 6144B per A array
#define BROW 272
#define BBUF (16*BROW)               // 4352B (single B array)
#define BOFF (2*ABUF)
#define STAGEB (2*ABUF + BBUF)       // 16640B
#define GEMM_SMEM (3*STAGEB)         // 49920B

__global__ void __launch_bounds__(512, 1) gemm_mma_kernel(const float* __restrict__ bias,
                                                          float* __restrict__ out) {
    extern __shared__ char smem[];
    const uint32_t sb = smem_u32(smem);

    const int tid  = threadIdx.x;
    const int lane = tid & 31;
    const int w    = tid >> 5;
    const int wm   = w >> 2;          // 0..3  (32-row group)
    const int wn   = w & 3;           // 0..3  (32-col group)
    const int l0 = blockIdx.x*128;
    const int h0 = blockIdx.y*128;
    const int b  = blockIdx.z;

    // ---- cp.async mappings (512 threads) ----
    // A: arr = tid>>8 (0: Wa, 1: Wg), rem = tid&255: row = rem>>1, seg = rem&1
    const int aarr = tid >> 8;
    const int arow = (tid & 255) >> 1, aseg = tid & 1;
    const __half* pA = g_Wh + (size_t)(aarr*Hh + h0 + arow)*Hh + aseg*8;
    const uint32_t aDst = (uint32_t)(aarr*ABUF + arow*AROW + aseg*16);
    // B: threads 0..255 only: brow = tid>>4, bch = tid&15
    const int brow = (tid >> 4) & 15, bch = tid & 15;
    const __half* pB = g_Yh + ((size_t)b*Hh + brow)*Ll + l0 + bch*8;
    const uint32_t bDst = (uint32_t)(BOFF + brow*BROW + bch*16);
    const bool doB = (tid < 256);

    const uint32_t a_off = (uint32_t)((lane & 15)*AROW + (lane >> 4)*16);
    const uint32_t b_off = (uint32_t)(((lane & 7) + ((lane >> 3) & 1)*8)*BROW
                                      + (lane >> 4)*16);

    float acc_a[2][4][4], acc_g[2][4][4];
    #pragma unroll
    for (int i = 0; i < 2; ++i)
        #pragma unroll
        for (int j = 0; j < 4; ++j)
            #pragma unroll
            for (int q = 0; q < 4; ++q) { acc_a[i][j][q] = 0.f; acc_g[i][j][q] = 0.f; }

    #pragma unroll
    for (int s = 0; s < 2; ++s) {
        uint32_t st = sb + (uint32_t)s*STAGEB;
        cpa16(st + aDst, pA + s*16);
        if (doB) cpa16(st + bDst, pB + (size_t)s*16*Ll);
        asm volatile("cp.async.commit_group;" ::: "memory");
    }

    int cur_s = 0;
    #pragma unroll 1
    for (int ks = 0; ks < 16; ++ks) {
        if (ks < 15) asm volatile("cp.async.wait_group 1;" ::: "memory");
        else         asm volatile("cp.async.wait_group 0;" ::: "memory");
        __syncthreads();
        if (ks + 2 < 16) {
            int s = ks + 2;
            int ss = cur_s + 2; if (ss >= 3) ss -= 3;
            uint32_t st = sb + (uint32_t)ss*STAGEB;
            cpa16(st + aDst, pA + s*16);
            if (doB) cpa16(st + bDst, pB + (size_t)s*16*Ll);
            asm volatile("cp.async.commit_group;" ::: "memory");
        }
        const uint32_t cur = sb + (uint32_t)cur_s*STAGEB;

        // ---- B fragments via ldmatrix.trans: 4 n8-blocks (32 cols) ----
        uint32_t bh[8];
        {
            uint32_t bas = cur + BOFF + b_off + (uint32_t)(wn*64);
            ldsm4t(&bh[0], bas);
            ldsm4t(&bh[4], bas + 32);
        }
        #pragma unroll
        for (int i = 0; i < 2; ++i) {
            uint32_t moff = (uint32_t)(wm*32 + i*16)*AROW + a_off;
            uint32_t aa[4], ag[4];
            ldsm4(aa, cur + 0*ABUF + moff);
            ldsm4(ag, cur + 1*ABUF + moff);
            #pragma unroll
            for (int j = 0; j < 4; ++j) {
                mma16816(acc_a[i][j], aa, bh[2*j], bh[2*j+1]);
                mma16816(acc_g[i][j], ag, bh[2*j], bh[2*j+1]);
            }
        }
        if (++cur_s == 3) cur_s = 0;
    }

    // ---- epilogue: bias + GLU, in-register ----
    #pragma unroll
    for (int i = 0; i < 2; ++i) {
        int hr = h0 + wm*32 + i*16 + (lane >> 2);
        float ba0 = bias[hr],     bg0 = bias[Hh + hr];
        float ba1 = bias[hr + 8], bg1 = bias[Hh + hr + 8];
        #pragma unroll
        for (int j = 0; j < 4; ++j) {
            int col = l0 + wn*32 + j*8 + (lane & 3)*2;
            float a0 = acc_a[i][j][0] + ba0, g0 = acc_g[i][j][0] + bg0;
            float a1 = acc_a[i][j][1] + ba0, g1 = acc_g[i][j][1] + bg0;
            float a2 = acc_a[i][j][2] + ba1, g2 = acc_g[i][j][2] + bg1;
            float a3 = acc_a[i][j][3] + ba1, g3 = acc_g[i][j][3] + bg1;
            float2 v0 = make_float2(a0 / (1.0f + expf(-g0)),
                                    a1 / (1.0f + expf(-g1)));
            float2 v1 = make_float2(a2 / (1.0f + expf(-g2)),
                                    a3 / (1.0f + expf(-g3)));
            *(float2*)(out + ((size_t)b*Hh + hr)*Ll + col)     = v0;
            *(float2*)(out + ((size_t)b*Hh + hr + 8)*Ll + col) = v1;
        }
    }
}

// ============================================================
extern "C" void kernel_launch(void* const* d_in, const int* in_sizes, int n_in,
                              void* d_out, int out_size) {
    const float* u       = (const float*)d_in[0];
    const float* log_dt  = (const float*)d_in[1];
    const float* C       = (const float*)d_in[2];
    const float* lar     = (const float*)d_in[3];
    const float* aim     = (const float*)d_in[4];
    const float* D       = (const float*)d_in[5];
    const float* Wm      = (const float*)d_in[6];
    const float* bias    = (const float*)d_in[7];
    float* out = (float*)d_out;

    cudaFuncSetAttribute(gemm_mma_kernel,
                         cudaFuncAttributeMaxDynamicSharedMemorySize, GEMM_SMEM);

    prep_kernel<<<(Hh*N2d + 255)/256, 256>>>(log_dt, C, lar, aim);
    wsplit_kernel<<<(2*Hh*Hh + 255)/256, 256>>>(Wm);
    scan_kernel<<<(Bb*Hh)/8, 256>>>(u, D);
    dim3 grid(Ll/128, Hh/128, Bb);
    gemm_mma_kernel<<<grid, 512, GEMM_SMEM>>>(bias, out);
}